// round 2
// baseline (speedup 1.0000x reference)
#include <cuda_runtime.h>
#include <cuda_bf16.h>
#include <cstdint>

// ---------------- problem constants ----------------
#define Bb   64
#define Tt   512
#define Ee   256
#define Hh   256
#define G4   1024          // 4*H
#define Oo   2

// ---------------- scratch (device globals: no runtime alloc) ----------------
__device__ float g_xproj[(size_t)Tt * Bb * G4];   // [t][b][gate] fp32, 128MB
__device__ float g_hf[Bb * Hh];                   // final forward hidden

__device__ __forceinline__ float sigm(float x) {
    return 1.0f / (1.0f + __expf(-x));
}

// =====================================================================
// Kernel 1: xproj = emb[x] @ W_ih_f^T + (b_ih_f + b_hh_f)
// M = T*B = 32768 (m = t*64 + b), N = 1024, K = 256
// =====================================================================
#define BM 128
#define BN 128
#define BK 8
__global__ __launch_bounds__(256) void xproj_kernel(
    const int* __restrict__ x,
    const float* __restrict__ emb,
    const float* __restrict__ wih,
    const float* __restrict__ bih,
    const float* __restrict__ bhh)
{
    __shared__ float As[BK][BM];
    __shared__ float Bs[BK][BN];

    const int bm = blockIdx.x;          // 0..255
    const int bn = blockIdx.y;          // 0..7
    const int tid = threadIdx.x;        // 0..255
    const int tx = tid & 15, ty = tid >> 4;

    // A loader: row = tid>>1 (0..127), half = tid&1 -> k offset 0 or 4
    const int arow = tid >> 1;
    const int ac4  = (tid & 1) * 4;
    const int m    = bm * BM + arow;
    const int bb   = m & 63;
    const int tt   = m >> 6;
    const int tok  = x[bb * Tt + tt];
    const float* aptr = emb + (size_t)tok * Ee;

    const int brow = tid >> 1;
    const int bc4  = (tid & 1) * 4;
    const float* bptr = wih + (size_t)(bn * BN + brow) * Ee;

    float acc[8][8];
#pragma unroll
    for (int i = 0; i < 8; i++)
#pragma unroll
        for (int j = 0; j < 8; j++) acc[i][j] = 0.0f;

    for (int k0 = 0; k0 < Ee; k0 += BK) {
        float4 av = *(const float4*)(aptr + k0 + ac4);
        float4 bv = *(const float4*)(bptr + k0 + bc4);
        __syncthreads();
        As[ac4 + 0][arow] = av.x; As[ac4 + 1][arow] = av.y;
        As[ac4 + 2][arow] = av.z; As[ac4 + 3][arow] = av.w;
        Bs[bc4 + 0][brow] = bv.x; Bs[bc4 + 1][brow] = bv.y;
        Bs[bc4 + 2][brow] = bv.z; Bs[bc4 + 3][brow] = bv.w;
        __syncthreads();
#pragma unroll
        for (int k = 0; k < BK; k++) {
            float a[8], b[8];
#pragma unroll
            for (int i = 0; i < 8; i += 4) {
                float4 v = *(const float4*)&As[k][ty * 8 + i];
                a[i] = v.x; a[i + 1] = v.y; a[i + 2] = v.z; a[i + 3] = v.w;
            }
#pragma unroll
            for (int j = 0; j < 8; j += 4) {
                float4 v = *(const float4*)&Bs[k][tx * 8 + j];
                b[j] = v.x; b[j + 1] = v.y; b[j + 2] = v.z; b[j + 3] = v.w;
            }
#pragma unroll
            for (int i = 0; i < 8; i++)
#pragma unroll
                for (int j = 0; j < 8; j++)
                    acc[i][j] = fmaf(a[i], b[j], acc[i][j]);
        }
    }

    const int gm = bm * BM + ty * 8;
    const int gn = bn * BN + tx * 8;
    float bias[8];
#pragma unroll
    for (int j = 0; j < 8; j++) bias[j] = bih[gn + j] + bhh[gn + j];
#pragma unroll
    for (int i = 0; i < 8; i++) {
        float* o = g_xproj + (size_t)(gm + i) * G4 + gn;
#pragma unroll
        for (int j0 = 0; j0 < 8; j0 += 4) {
            float4 v;
            v.x = acc[i][j0 + 0] + bias[j0 + 0];
            v.y = acc[i][j0 + 1] + bias[j0 + 1];
            v.z = acc[i][j0 + 2] + bias[j0 + 2];
            v.w = acc[i][j0 + 3] + bias[j0 + 3];
            *(float4*)(o + j0) = v;
        }
    }
}

// =====================================================================
// Kernel 2: forward LSTM recurrence, 16 clusters x 8 CTAs (128 CTAs).
// Cluster cl handles batches cl*4..cl*4+3; CTA rank j owns h cols
// [32j, 32j+32) -> 128 gate rows, weights held in registers.
// =====================================================================
__global__ void __cluster_dims__(8, 1, 1) __launch_bounds__(512, 1)
lstm_fwd_kernel(const float* __restrict__ whh)
{
    __shared__ __align__(16) float s_h[2][4][Hh];    // double-buffered hidden (full 256)
    __shared__ float s_z[4][128];                    // Whh@h partial results
    __shared__ __align__(16) float s_xp[2][4][128];  // prefetched xproj slice
    __shared__ float s_c[4][32];                     // cell state (own cols)

    const int tid = threadIdx.x;                     // 0..511
    const int j   = blockIdx.x & 7;                  // cluster rank
    const int cl  = blockIdx.x >> 3;                 // cluster id (batch group)

    const int rp = tid >> 3;                         // row pair 0..63
    const int kc = tid & 7;                          // k chunk 0..7 (32 k each)
    const int r0 = 2 * rp, r1 = 2 * rp + 1;
    const int kbase = kc * 32;

    // global gate rows: gate = r>>5, col = j*32 + (r&31)
    const int grow0 = ((r0 >> 5) << 8) + j * 32 + (r0 & 31);
    const int grow1 = ((r1 >> 5) << 8) + j * 32 + (r1 & 31);

    // weights into registers: 2 rows x 32 k
    float w0[32], w1[32];
    {
        const float4* p0 = (const float4*)(whh + (size_t)grow0 * Hh + kbase);
        const float4* p1 = (const float4*)(whh + (size_t)grow1 * Hh + kbase);
#pragma unroll
        for (int q = 0; q < 8; q++) {
            float4 v = p0[q];
            w0[4*q] = v.x; w0[4*q+1] = v.y; w0[4*q+2] = v.z; w0[4*q+3] = v.w;
            float4 u = p1[q];
            w1[4*q] = u.x; w1[4*q+1] = u.y; w1[4*q+2] = u.z; w1[4*q+3] = u.w;
        }
    }

    // init h=0 (parity 0 only), c=0
    for (int i = tid; i < 4 * Hh; i += 512) ((float*)s_h[0])[i] = 0.0f;
    if (tid < 128) s_c[tid >> 5][tid & 31] = 0.0f;

    const uint32_t s_xp_addr = (uint32_t)__cvta_generic_to_shared(&s_xp[0][0][0]);
    const uint32_t s_h_addr  = (uint32_t)__cvta_generic_to_shared(&s_h[0][0][0]);

    // prefetch xproj slice for t=0 into parity 0
    if (tid < 128) {
        int seg = tid >> 3, off = (tid & 7) * 4;
        int bl = seg >> 2, g = seg & 3;
        const float* src = g_xproj + ((size_t)0 * Bb + cl * 4 + bl) * G4 + g * 256 + j * 32 + off;
        uint32_t dst = s_xp_addr + (uint32_t)(((0 * 4 + bl) * 128) + g * 32 + off) * 4u;
        asm volatile("cp.async.ca.shared.global [%0], [%1], 16;" :: "r"(dst), "l"(src));
    }
    asm volatile("cp.async.commit_group;" ::: "memory");

    __syncthreads();
    asm volatile("barrier.cluster.arrive.aligned;" ::: "memory");
    asm volatile("barrier.cluster.wait.aligned;"   ::: "memory");

    for (int t = 0; t < Tt; t++) {
        const int cur = t & 1, nxt = cur ^ 1;

        // prefetch next step's xproj slice
        if (tid < 128) {
            int tn = (t + 1 < Tt) ? t + 1 : (Tt - 1);
            int seg = tid >> 3, off = (tid & 7) * 4;
            int bl = seg >> 2, g = seg & 3;
            const float* src = g_xproj + ((size_t)tn * Bb + cl * 4 + bl) * G4 + g * 256 + j * 32 + off;
            uint32_t dst = s_xp_addr + (uint32_t)(((nxt * 4 + bl) * 128) + g * 32 + off) * 4u;
            asm volatile("cp.async.ca.shared.global [%0], [%1], 16;" :: "r"(dst), "l"(src));
        }
        asm volatile("cp.async.commit_group;" ::: "memory");

        // dot product: acc[row][batch], h broadcast from smem
        float a0[4] = {0, 0, 0, 0}, a1[4] = {0, 0, 0, 0};
#pragma unroll
        for (int q = 0; q < 8; q++) {
            float4 hv[4];
#pragma unroll
            for (int bl = 0; bl < 4; bl++)
                hv[bl] = *(const float4*)&s_h[cur][bl][kbase + q * 4];
#pragma unroll
            for (int bl = 0; bl < 4; bl++) {
                a0[bl] = fmaf(w0[4*q+0], hv[bl].x, a0[bl]);
                a0[bl] = fmaf(w0[4*q+1], hv[bl].y, a0[bl]);
                a0[bl] = fmaf(w0[4*q+2], hv[bl].z, a0[bl]);
                a0[bl] = fmaf(w0[4*q+3], hv[bl].w, a0[bl]);
                a1[bl] = fmaf(w1[4*q+0], hv[bl].x, a1[bl]);
                a1[bl] = fmaf(w1[4*q+1], hv[bl].y, a1[bl]);
                a1[bl] = fmaf(w1[4*q+2], hv[bl].z, a1[bl]);
                a1[bl] = fmaf(w1[4*q+3], hv[bl].w, a1[bl]);
            }
        }
        // reduce across 8 k-lanes
#pragma unroll
        for (int s = 4; s > 0; s >>= 1) {
#pragma unroll
            for (int bl = 0; bl < 4; bl++) {
                a0[bl] += __shfl_down_sync(0xffffffffu, a0[bl], s, 8);
                a1[bl] += __shfl_down_sync(0xffffffffu, a1[bl], s, 8);
            }
        }
        if (kc == 0) {
#pragma unroll
            for (int bl = 0; bl < 4; bl++) {
                s_z[bl][r0] = a0[bl];
                s_z[bl][r1] = a1[bl];
            }
        }
        asm volatile("cp.async.wait_group 1;" ::: "memory");
        __syncthreads();

        // gate phase: 128 threads = 4 batches x 32 own cols
        if (tid < 128) {
            const int bl = tid >> 5, col = tid & 31;
            float zi = s_z[bl][col]       + s_xp[cur][bl][col];
            float zf = s_z[bl][32 + col]  + s_xp[cur][bl][32 + col];
            float zg = s_z[bl][64 + col]  + s_xp[cur][bl][64 + col];
            float zo = s_z[bl][96 + col]  + s_xp[cur][bl][96 + col];
            float c  = sigm(zf) * s_c[bl][col] + sigm(zi) * tanhf(zg);
            s_c[bl][col] = c;
            float h  = sigm(zo) * tanhf(c);

            uint32_t laddr = s_h_addr +
                (uint32_t)(((nxt * 4 + bl) * Hh) + j * 32 + col) * 4u;
#pragma unroll
            for (int p = 0; p < 8; p++) {
                uint32_t ra;
                asm("mapa.shared::cluster.u32 %0, %1, %2;" : "=r"(ra) : "r"(laddr), "r"(p));
                asm volatile("st.shared::cluster.f32 [%0], %1;" :: "r"(ra), "f"(h));
            }
            if (t == Tt - 1)
                g_hf[(cl * 4 + bl) * Hh + j * 32 + col] = h;
        }
        asm volatile("barrier.cluster.arrive.aligned;" ::: "memory");
        asm volatile("barrier.cluster.wait.aligned;"   ::: "memory");
    }
}

// =====================================================================
// Kernel 3: backward LSTM (single step, h=c=0) + fc1(relu) + fc2
// one CTA per batch element, 256 threads
// =====================================================================
__global__ __launch_bounds__(256) void head_kernel(
    const int* __restrict__ x,
    const float* __restrict__ emb,
    const float* __restrict__ wihb,
    const float* __restrict__ bihb,
    const float* __restrict__ bhhb,
    const float* __restrict__ fc1w,
    const float* __restrict__ fc1b,
    const float* __restrict__ fc2w,
    const float* __restrict__ fc2b,
    float* __restrict__ out)
{
    __shared__ __align__(16) float s_e[Ee];
    __shared__ float s_lo[2 * Hh];
    __shared__ float s_f1[24];

    const int b = blockIdx.x;
    const int tid = threadIdx.x;

    const int tok = x[b * Tt + (Tt - 1)];
    s_e[tid]  = emb[(size_t)tok * Ee + tid];
    s_lo[tid] = g_hf[b * Hh + tid];   // forward hidden = first half
    __syncthreads();

    // z rows: tid (i), 256+tid (f), 512+tid (g), 768+tid (o)
    float zi = bihb[tid]       + bhhb[tid];
    float zg = bihb[512 + tid] + bhhb[512 + tid];
    float zo = bihb[768 + tid] + bhhb[768 + tid];
    const float4* wi = (const float4*)(wihb + (size_t)tid * Ee);
    const float4* wg = (const float4*)(wihb + (size_t)(512 + tid) * Ee);
    const float4* wo = (const float4*)(wihb + (size_t)(768 + tid) * Ee);
    const float4* ev = (const float4*)s_e;
#pragma unroll 4
    for (int q = 0; q < Ee / 4; q++) {
        float4 e4 = ev[q];
        float4 vi = wi[q], vg = wg[q], vo = wo[q];
        zi += vi.x * e4.x + vi.y * e4.y + vi.z * e4.z + vi.w * e4.w;
        zg += vg.x * e4.x + vg.y * e4.y + vg.z * e4.z + vg.w * e4.w;
        zo += vo.x * e4.x + vo.y * e4.y + vo.z * e4.z + vo.w * e4.w;
    }
    // c_prev = 0, so the forget gate contributes nothing
    float c = sigm(zi) * tanhf(zg);
    float h = sigm(zo) * tanhf(c);
    s_lo[Hh + tid] = h;
    __syncthreads();

    if (tid < 24) {
        float s = fc1b[tid];
        const float* w = fc1w + (size_t)tid * (2 * Hh);
#pragma unroll 8
        for (int k = 0; k < 2 * Hh; k++) s = fmaf(w[k], s_lo[k], s);
        s_f1[tid] = fmaxf(s, 0.0f);
    }
    __syncthreads();
    if (tid < Oo) {
        float s = fc2b[tid];
        const float* w = fc2w + (size_t)tid * 24;
#pragma unroll
        for (int k = 0; k < 24; k++) s = fmaf(w[k], s_f1[k], s);
        out[b * Oo + tid] = s;
    }
}

// =====================================================================
// launch
// =====================================================================
extern "C" void kernel_launch(void* const* d_in, const int* in_sizes, int n_in,
                              void* d_out, int out_size)
{
    const int* x           = (const int*)d_in[0];
    const float* emb       = (const float*)d_in[1];
    const float* w_ih_f    = (const float*)d_in[2];
    const float* w_hh_f    = (const float*)d_in[3];
    const float* b_ih_f    = (const float*)d_in[4];
    const float* b_hh_f    = (const float*)d_in[5];
    const float* w_ih_b    = (const float*)d_in[6];
    // d_in[7] = w_hh_b (unused: backward dir is a single step from h=0)
    const float* b_ih_b    = (const float*)d_in[8];
    const float* b_hh_b    = (const float*)d_in[9];
    const float* fc1_w     = (const float*)d_in[10];
    const float* fc1_b     = (const float*)d_in[11];
    const float* fc2_w     = (const float*)d_in[12];
    const float* fc2_b     = (const float*)d_in[13];
    float* out             = (float*)d_out;

    dim3 gemm_grid(Tt * Bb / BM, G4 / BN);   // (256, 8)
    xproj_kernel<<<gemm_grid, 256>>>(x, emb, w_ih_f, b_ih_f, b_hh_f);

    lstm_fwd_kernel<<<128, 512>>>(w_hh_f);

    head_kernel<<<Bb, 256>>>(x, emb, w_ih_b, b_ih_b, b_hh_b,
                             fc1_w, fc1_b, fc2_w, fc2_b, out);
}

// round 3
// speedup vs baseline: 1.0275x; 1.0275x over previous
#include <cuda_runtime.h>
#include <cuda_bf16.h>
#include <cstdint>

// ---------------- problem constants ----------------
#define Bb   64
#define Tt   512
#define Ee   256
#define Hh   256
#define G4   1024          // 4*H
#define Oo   2

// ---------------- scratch (device globals: no runtime alloc) ----------------
__device__ float g_xproj[(size_t)Tt * Bb * G4];   // [t][b][gate] fp32, 128MB
__device__ float g_hf[Bb * Hh];                   // final forward hidden

__device__ __forceinline__ float sigm(float x) {
    return __fdividef(1.0f, 1.0f + __expf(-x));
}
__device__ __forceinline__ float tanh_fast(float x) {
    return __fdividef(2.0f, 1.0f + __expf(-2.0f * x)) - 1.0f;
}

// =====================================================================
// Kernel 1: xproj = emb[x] @ W_ih_f^T + (b_ih_f + b_hh_f)
// M = T*B = 32768 (m = t*64 + b), N = 1024, K = 256
// =====================================================================
#define BM 128
#define BN 128
#define BK 8
__global__ __launch_bounds__(256) void xproj_kernel(
    const int* __restrict__ x,
    const float* __restrict__ emb,
    const float* __restrict__ wih,
    const float* __restrict__ bih,
    const float* __restrict__ bhh)
{
    __shared__ float As[BK][BM];
    __shared__ float Bs[BK][BN];

    const int bm = blockIdx.x;
    const int bn = blockIdx.y;
    const int tid = threadIdx.x;
    const int tx = tid & 15, ty = tid >> 4;

    const int arow = tid >> 1;
    const int ac4  = (tid & 1) * 4;
    const int m    = bm * BM + arow;
    const int bb   = m & 63;
    const int tt   = m >> 6;
    const int tok  = x[bb * Tt + tt];
    const float* aptr = emb + (size_t)tok * Ee;

    const int brow = tid >> 1;
    const int bc4  = (tid & 1) * 4;
    const float* bptr = wih + (size_t)(bn * BN + brow) * Ee;

    float acc[8][8];
#pragma unroll
    for (int i = 0; i < 8; i++)
#pragma unroll
        for (int j = 0; j < 8; j++) acc[i][j] = 0.0f;

    for (int k0 = 0; k0 < Ee; k0 += BK) {
        float4 av = *(const float4*)(aptr + k0 + ac4);
        float4 bv = *(const float4*)(bptr + k0 + bc4);
        __syncthreads();
        As[ac4 + 0][arow] = av.x; As[ac4 + 1][arow] = av.y;
        As[ac4 + 2][arow] = av.z; As[ac4 + 3][arow] = av.w;
        Bs[bc4 + 0][brow] = bv.x; Bs[bc4 + 1][brow] = bv.y;
        Bs[bc4 + 2][brow] = bv.z; Bs[bc4 + 3][brow] = bv.w;
        __syncthreads();
#pragma unroll
        for (int k = 0; k < BK; k++) {
            float a[8], b[8];
#pragma unroll
            for (int i = 0; i < 8; i += 4) {
                float4 v = *(const float4*)&As[k][ty * 8 + i];
                a[i] = v.x; a[i + 1] = v.y; a[i + 2] = v.z; a[i + 3] = v.w;
            }
#pragma unroll
            for (int j = 0; j < 8; j += 4) {
                float4 v = *(const float4*)&Bs[k][tx * 8 + j];
                b[j] = v.x; b[j + 1] = v.y; b[j + 2] = v.z; b[j + 3] = v.w;
            }
#pragma unroll
            for (int i = 0; i < 8; i++)
#pragma unroll
                for (int j = 0; j < 8; j++)
                    acc[i][j] = fmaf(a[i], b[j], acc[i][j]);
        }
    }

    const int gm = bm * BM + ty * 8;
    const int gn = bn * BN + tx * 8;
    float bias[8];
#pragma unroll
    for (int j = 0; j < 8; j++) bias[j] = bih[gn + j] + bhh[gn + j];
#pragma unroll
    for (int i = 0; i < 8; i++) {
        float* o = g_xproj + (size_t)(gm + i) * G4 + gn;
#pragma unroll
        for (int j0 = 0; j0 < 8; j0 += 4) {
            float4 v;
            v.x = acc[i][j0 + 0] + bias[j0 + 0];
            v.y = acc[i][j0 + 1] + bias[j0 + 1];
            v.z = acc[i][j0 + 2] + bias[j0 + 2];
            v.w = acc[i][j0 + 3] + bias[j0 + 3];
            *(float4*)(o + j0) = v;
        }
    }
}

// =====================================================================
// Kernel 2: forward LSTM recurrence, 16 clusters x 8 CTAs.
// Per-step sync: cp.async.bulk S2S-cluster + mbarrier complete_tx
// (NO barrier.cluster / L1-flush in the loop).
// FMA via packed fma.rn.f32x2 (2 MACs / instr).
// =====================================================================
__device__ __forceinline__ void mbar_wait_cluster(uint32_t mbar, uint32_t parity) {
    asm volatile(
        "{\n\t"
        ".reg .pred P;\n\t"
        "WAIT_%=:\n\t"
        "mbarrier.try_wait.parity.acquire.cluster.shared::cta.b64 P, [%0], %1, 0x989680;\n\t"
        "@P bra DONE_%=;\n\t"
        "bra WAIT_%=;\n\t"
        "DONE_%=:\n\t"
        "}"
        :: "r"(mbar), "r"(parity) : "memory");
}

__global__ void __cluster_dims__(8, 1, 1) __launch_bounds__(512, 1)
lstm_fwd_kernel(const float* __restrict__ whh)
{
    // h double-buffered, laid out so each source CTA's block is contiguous:
    // s_h[parity][srcCTA j][bl 0..3][col 0..31]  (512B per (parity, j))
    __shared__ __align__(16) float s_h[2][8][4][32];
    __shared__ float s_z[4][128];                    // Whh@h results
    __shared__ __align__(16) float s_xp[2][4][128];  // prefetched xproj slice
    __shared__ float s_c[4][32];                     // cell state (own cols)
    __shared__ __align__(16) float s_out[4][32];     // staged outgoing h block
    __shared__ __align__(8) unsigned long long s_mbar[2];

    const int tid = threadIdx.x;                     // 0..511
    const int j   = blockIdx.x & 7;                  // cluster rank
    const int cl  = blockIdx.x >> 3;                 // batch group

    const int rp = tid >> 3;                         // row pair 0..63
    const int kc = tid & 7;                          // k chunk 0..7
    const int r0 = 2 * rp, r1 = 2 * rp + 1;
    const int kbase = kc * 32;

    const int grow0 = ((r0 >> 5) << 8) + j * 32 + (r0 & 31);
    const int grow1 = ((r1 >> 5) << 8) + j * 32 + (r1 & 31);

    // weights as packed f32x2 pairs (k-adjacent): 16 u64 per row
    unsigned long long w0p[16], w1p[16];
#pragma unroll
    for (int q = 0; q < 8; q++) {
        ulonglong2 t0 = *(const ulonglong2*)(whh + (size_t)grow0 * Hh + kbase + q * 4);
        ulonglong2 t1 = *(const ulonglong2*)(whh + (size_t)grow1 * Hh + kbase + q * 4);
        w0p[2*q] = t0.x; w0p[2*q+1] = t0.y;
        w1p[2*q] = t1.x; w1p[2*q+1] = t1.y;
    }

    // init: h(0)=0 (parity 0), c=0, mbarriers
    for (int i = tid; i < 8 * 4 * 32; i += 512) ((float*)s_h[0])[i] = 0.0f;
    if (tid < 128) s_c[tid >> 5][tid & 31] = 0.0f;

    const uint32_t s_h_addr   = (uint32_t)__cvta_generic_to_shared(&s_h[0][0][0][0]);
    const uint32_t s_xp_addr  = (uint32_t)__cvta_generic_to_shared(&s_xp[0][0][0]);
    const uint32_t s_out_addr = (uint32_t)__cvta_generic_to_shared(&s_out[0][0]);
    const uint32_t mbar_addr  = (uint32_t)__cvta_generic_to_shared(&s_mbar[0]);

    if (tid == 0) {
        asm volatile("mbarrier.init.shared.b64 [%0], 1;" :: "r"(mbar_addr) : "memory");
        asm volatile("mbarrier.init.shared.b64 [%0], 1;" :: "r"(mbar_addr + 8) : "memory");
    }

    // prefetch xproj slice for t=0 into parity 0
    if (tid < 128) {
        int seg = tid >> 3, off = (tid & 7) * 4;
        int bl = seg >> 2, g = seg & 3;
        const float* src = g_xproj + ((size_t)0 * Bb + cl * 4 + bl) * G4 + g * 256 + j * 32 + off;
        uint32_t dst = s_xp_addr + (uint32_t)((bl * 128) + g * 32 + off) * 4u;
        asm volatile("cp.async.ca.shared.global [%0], [%1], 16;" :: "r"(dst), "l"(src));
    }
    asm volatile("cp.async.commit_group;" ::: "memory");

    __syncthreads();
    // one-time cluster sync: mbarrier inits visible before any peer sends
    asm volatile("barrier.cluster.arrive.aligned;" ::: "memory");
    asm volatile("barrier.cluster.wait.aligned;"   ::: "memory");

    for (int t = 0; t < Tt; t++) {
        const int cur = t & 1, nxt = cur ^ 1;

        // wait for this step's h (h(0) prefilled locally)
        if (t > 0) {
            int ph = (t & 1) ? ((t >> 1) & 1) : (((t >> 1) + 1) & 1);
            mbar_wait_cluster(mbar_addr + (uint32_t)(t & 1) * 8, (uint32_t)ph);
        }

        // prefetch next step's xproj slice
        if (tid < 128) {
            int tn = (t + 1 < Tt) ? t + 1 : (Tt - 1);
            int seg = tid >> 3, off = (tid & 7) * 4;
            int bl = seg >> 2, g = seg & 3;
            const float* src = g_xproj + ((size_t)tn * Bb + cl * 4 + bl) * G4 + g * 256 + j * 32 + off;
            uint32_t dst = s_xp_addr + (uint32_t)(((nxt * 4 + bl) * 128) + g * 32 + off) * 4u;
            asm volatile("cp.async.ca.shared.global [%0], [%1], 16;" :: "r"(dst), "l"(src));
        }
        asm volatile("cp.async.commit_group;" ::: "memory");

        // ---- Whh @ h via packed f32x2 FMAs ----
        unsigned long long a0[4] = {0, 0, 0, 0};
        unsigned long long a1[4] = {0, 0, 0, 0};
        const float* hbase = &s_h[cur][kc][0][0];
#pragma unroll
        for (int q = 0; q < 8; q++) {
#pragma unroll
            for (int bl = 0; bl < 4; bl++) {
                ulonglong2 h2 = *(const ulonglong2*)(hbase + bl * 32 + q * 4);
                asm("fma.rn.f32x2 %0, %1, %2, %0;" : "+l"(a0[bl]) : "l"(w0p[2*q]),   "l"(h2.x));
                asm("fma.rn.f32x2 %0, %1, %2, %0;" : "+l"(a0[bl]) : "l"(w0p[2*q+1]), "l"(h2.y));
                asm("fma.rn.f32x2 %0, %1, %2, %0;" : "+l"(a1[bl]) : "l"(w1p[2*q]),   "l"(h2.x));
                asm("fma.rn.f32x2 %0, %1, %2, %0;" : "+l"(a1[bl]) : "l"(w1p[2*q+1]), "l"(h2.y));
            }
        }
        float f0[4], f1[4];
#pragma unroll
        for (int bl = 0; bl < 4; bl++) {
            f0[bl] = __uint_as_float((unsigned)a0[bl]) + __uint_as_float((unsigned)(a0[bl] >> 32));
            f1[bl] = __uint_as_float((unsigned)a1[bl]) + __uint_as_float((unsigned)(a1[bl] >> 32));
        }
        // reduce across 8 k-lanes
#pragma unroll
        for (int s = 4; s > 0; s >>= 1) {
#pragma unroll
            for (int bl = 0; bl < 4; bl++) {
                f0[bl] += __shfl_down_sync(0xffffffffu, f0[bl], s, 8);
                f1[bl] += __shfl_down_sync(0xffffffffu, f1[bl], s, 8);
            }
        }
        if (kc == 0) {
#pragma unroll
            for (int bl = 0; bl < 4; bl++) {
                s_z[bl][r0] = f0[bl];
                s_z[bl][r1] = f1[bl];
            }
        }
        asm volatile("cp.async.wait_group 1;" ::: "memory");
        __syncthreads();   // s_z ready; all h(cur) reads complete

        // ---- gate phase: 128 threads = 4 batches x 32 own cols ----
        if (tid < 128) {
            const int bl = tid >> 5, col = tid & 31;
            float zi = s_z[bl][col]       + s_xp[cur][bl][col];
            float zf = s_z[bl][32 + col]  + s_xp[cur][bl][32 + col];
            float zg = s_z[bl][64 + col]  + s_xp[cur][bl][64 + col];
            float zo = s_z[bl][96 + col]  + s_xp[cur][bl][96 + col];
            float c  = sigm(zf) * s_c[bl][col] + sigm(zi) * tanh_fast(zg);
            s_c[bl][col] = c;
            float h  = sigm(zo) * tanh_fast(c);
            s_out[bl][col] = h;
            if (t == Tt - 1)
                g_hf[(cl * 4 + bl) * Hh + j * 32 + col] = h;
        }
        __syncthreads();   // s_out fully staged

        // ---- broadcast h(t+1): 8x 512B bulk copies + mbarrier complete_tx ----
        if (t < Tt - 1 && tid == 0) {
            asm volatile("fence.proxy.async.shared::cta;" ::: "memory");
            uint32_t mb_next = mbar_addr + (uint32_t)nxt * 8;
            asm volatile("mbarrier.arrive.expect_tx.shared.b64 _, [%0], %1;"
                         :: "r"(mb_next), "r"(4096) : "memory");
            uint32_t ldst = s_h_addr + (uint32_t)(nxt * 8 + j) * 512u;
#pragma unroll
            for (int p = 0; p < 8; p++) {
                uint32_t rd, rm;
                asm("mapa.shared::cluster.u32 %0, %1, %2;" : "=r"(rd) : "r"(ldst), "r"(p));
                asm("mapa.shared::cluster.u32 %0, %1, %2;" : "=r"(rm) : "r"(mb_next), "r"(p));
                asm volatile(
                    "cp.async.bulk.shared::cluster.shared::cta.mbarrier::complete_tx::bytes "
                    "[%0], [%1], %2, [%3];"
                    :: "r"(rd), "r"(s_out_addr), "r"(512), "r"(rm) : "memory");
            }
        }
    }
}

// =====================================================================
// Kernel 3: backward LSTM (single step, h=c=0) + fc1(relu) + fc2
// =====================================================================
__global__ __launch_bounds__(256) void head_kernel(
    const int* __restrict__ x,
    const float* __restrict__ emb,
    const float* __restrict__ wihb,
    const float* __restrict__ bihb,
    const float* __restrict__ bhhb,
    const float* __restrict__ fc1w,
    const float* __restrict__ fc1b,
    const float* __restrict__ fc2w,
    const float* __restrict__ fc2b,
    float* __restrict__ out)
{
    __shared__ __align__(16) float s_e[Ee];
    __shared__ float s_lo[2 * Hh];
    __shared__ float s_f1[24];

    const int b = blockIdx.x;
    const int tid = threadIdx.x;

    const int tok = x[b * Tt + (Tt - 1)];
    s_e[tid]  = emb[(size_t)tok * Ee + tid];
    s_lo[tid] = g_hf[b * Hh + tid];
    __syncthreads();

    float zi = bihb[tid]       + bhhb[tid];
    float zg = bihb[512 + tid] + bhhb[512 + tid];
    float zo = bihb[768 + tid] + bhhb[768 + tid];
    const float4* wi = (const float4*)(wihb + (size_t)tid * Ee);
    const float4* wg = (const float4*)(wihb + (size_t)(512 + tid) * Ee);
    const float4* wo = (const float4*)(wihb + (size_t)(768 + tid) * Ee);
    const float4* ev = (const float4*)s_e;
#pragma unroll 4
    for (int q = 0; q < Ee / 4; q++) {
        float4 e4 = ev[q];
        float4 vi = wi[q], vg = wg[q], vo = wo[q];
        zi += vi.x * e4.x + vi.y * e4.y + vi.z * e4.z + vi.w * e4.w;
        zg += vg.x * e4.x + vg.y * e4.y + vg.z * e4.z + vg.w * e4.w;
        zo += vo.x * e4.x + vo.y * e4.y + vo.z * e4.z + vo.w * e4.w;
    }
    float c = sigm(zi) * tanhf(zg);   // c_prev = 0: forget gate drops out
    float h = sigm(zo) * tanhf(c);
    s_lo[Hh + tid] = h;
    __syncthreads();

    if (tid < 24) {
        float s = fc1b[tid];
        const float* w = fc1w + (size_t)tid * (2 * Hh);
#pragma unroll 8
        for (int k = 0; k < 2 * Hh; k++) s = fmaf(w[k], s_lo[k], s);
        s_f1[tid] = fmaxf(s, 0.0f);
    }
    __syncthreads();
    if (tid < Oo) {
        float s = fc2b[tid];
        const float* w = fc2w + (size_t)tid * 24;
#pragma unroll
        for (int k = 0; k < 24; k++) s = fmaf(w[k], s_f1[k], s);
        out[b * Oo + tid] = s;
    }
}

// =====================================================================
// launch
// =====================================================================
extern "C" void kernel_launch(void* const* d_in, const int* in_sizes, int n_in,
                              void* d_out, int out_size)
{
    const int* x           = (const int*)d_in[0];
    const float* emb       = (const float*)d_in[1];
    const float* w_ih_f    = (const float*)d_in[2];
    const float* w_hh_f    = (const float*)d_in[3];
    const float* b_ih_f    = (const float*)d_in[4];
    const float* b_hh_f    = (const float*)d_in[5];
    const float* w_ih_b    = (const float*)d_in[6];
    // d_in[7] = w_hh_b (unused: backward dir is a single step from h=0)
    const float* b_ih_b    = (const float*)d_in[8];
    const float* b_hh_b    = (const float*)d_in[9];
    const float* fc1_w     = (const float*)d_in[10];
    const float* fc1_b     = (const float*)d_in[11];
    const float* fc2_w     = (const float*)d_in[12];
    const float* fc2_b     = (const float*)d_in[13];
    float* out             = (float*)d_out;

    dim3 gemm_grid(Tt * Bb / BM, G4 / BN);   // (256, 8)
    xproj_kernel<<<gemm_grid, 256>>>(x, emb, w_ih_f, b_ih_f, b_hh_f);

    lstm_fwd_kernel<<<128, 512>>>(w_hh_f);

    head_kernel<<<Bb, 256>>>(x, emb, w_ih_b, b_ih_b, b_hh_b,
                             fc1_w, fc1_b, fc2_w, fc2_b, out);
}

// round 4
// speedup vs baseline: 4.1013x; 3.9917x over previous
#include <cuda_runtime.h>
#include <cuda_bf16.h>
#include <cstdint>

// ---------------- problem constants ----------------
#define Bb   64
#define Tt   512
#define Ee   256
#define Hh   256
#define G4   1024          // 4*H
#define Oo   2

// ---------------- scratch (device globals: no runtime alloc) ----------------
__device__ float g_xproj[(size_t)Tt * Bb * G4];   // [t][b][gate] fp32, 128MB
__device__ float g_hf[Bb * Hh];                   // final forward hidden

__device__ __forceinline__ float sigm(float x) {
    return __fdividef(1.0f, 1.0f + __expf(-x));
}
__device__ __forceinline__ float tanh_fast(float x) {
    return __fdividef(2.0f, 1.0f + __expf(-2.0f * x)) - 1.0f;
}

// =====================================================================
// Kernel 1: xproj = emb[x] @ W_ih_f^T + (b_ih_f + b_hh_f)
// =====================================================================
#define BM 128
#define BN 128
#define BK 8
__global__ __launch_bounds__(256) void xproj_kernel(
    const int* __restrict__ x,
    const float* __restrict__ emb,
    const float* __restrict__ wih,
    const float* __restrict__ bih,
    const float* __restrict__ bhh)
{
    __shared__ float As[BK][BM];
    __shared__ float Bs[BK][BN];

    const int bm = blockIdx.x;
    const int bn = blockIdx.y;
    const int tid = threadIdx.x;
    const int tx = tid & 15, ty = tid >> 4;

    const int arow = tid >> 1;
    const int ac4  = (tid & 1) * 4;
    const int m    = bm * BM + arow;
    const int bb   = m & 63;
    const int tt   = m >> 6;
    const int tok  = x[bb * Tt + tt];
    const float* aptr = emb + (size_t)tok * Ee;

    const int brow = tid >> 1;
    const int bc4  = (tid & 1) * 4;
    const float* bptr = wih + (size_t)(bn * BN + brow) * Ee;

    float acc[8][8];
#pragma unroll
    for (int i = 0; i < 8; i++)
#pragma unroll
        for (int j = 0; j < 8; j++) acc[i][j] = 0.0f;

    for (int k0 = 0; k0 < Ee; k0 += BK) {
        float4 av = *(const float4*)(aptr + k0 + ac4);
        float4 bv = *(const float4*)(bptr + k0 + bc4);
        __syncthreads();
        As[ac4 + 0][arow] = av.x; As[ac4 + 1][arow] = av.y;
        As[ac4 + 2][arow] = av.z; As[ac4 + 3][arow] = av.w;
        Bs[bc4 + 0][brow] = bv.x; Bs[bc4 + 1][brow] = bv.y;
        Bs[bc4 + 2][brow] = bv.z; Bs[bc4 + 3][brow] = bv.w;
        __syncthreads();
#pragma unroll
        for (int k = 0; k < BK; k++) {
            float a[8], b[8];
#pragma unroll
            for (int i = 0; i < 8; i += 4) {
                float4 v = *(const float4*)&As[k][ty * 8 + i];
                a[i] = v.x; a[i + 1] = v.y; a[i + 2] = v.z; a[i + 3] = v.w;
            }
#pragma unroll
            for (int j = 0; j < 8; j += 4) {
                float4 v = *(const float4*)&Bs[k][tx * 8 + j];
                b[j] = v.x; b[j + 1] = v.y; b[j + 2] = v.z; b[j + 3] = v.w;
            }
#pragma unroll
            for (int i = 0; i < 8; i++)
#pragma unroll
                for (int j = 0; j < 8; j++)
                    acc[i][j] = fmaf(a[i], b[j], acc[i][j]);
        }
    }

    const int gm = bm * BM + ty * 8;
    const int gn = bn * BN + tx * 8;
    float bias[8];
#pragma unroll
    for (int j = 0; j < 8; j++) bias[j] = bih[gn + j] + bhh[gn + j];
#pragma unroll
    for (int i = 0; i < 8; i++) {
        float* o = g_xproj + (size_t)(gm + i) * G4 + gn;
#pragma unroll
        for (int j0 = 0; j0 < 8; j0 += 4) {
            float4 v;
            v.x = acc[i][j0 + 0] + bias[j0 + 0];
            v.y = acc[i][j0 + 1] + bias[j0 + 1];
            v.z = acc[i][j0 + 2] + bias[j0 + 2];
            v.w = acc[i][j0 + 3] + bias[j0 + 3];
            *(float4*)(o + j0) = v;
        }
    }
}

// =====================================================================
// Kernel 2: forward LSTM recurrence, 16 clusters x 8 CTAs.
// h blocks padded to 560B stride (bank-conflict-free kc reads).
// Per-warp 128B bulk sends; one __syncthreads per step.
// =====================================================================
#define J_STRIDE   560               // bytes per src-CTA h block (512 used + pad)
#define PAR_STRIDE (8 * J_STRIDE)    // 4480 bytes per parity

__device__ __forceinline__ void mbar_wait_cluster(uint32_t mbar, uint32_t parity) {
    asm volatile(
        "{\n\t"
        ".reg .pred P;\n\t"
        "WAIT_%=:\n\t"
        "mbarrier.try_wait.parity.acquire.cluster.shared::cta.b64 P, [%0], %1, 0x989680;\n\t"
        "@P bra DONE_%=;\n\t"
        "bra WAIT_%=;\n\t"
        "DONE_%=:\n\t"
        "}"
        :: "r"(mbar), "r"(parity) : "memory");
}

__global__ void __cluster_dims__(8, 1, 1) __launch_bounds__(512, 1)
lstm_fwd_kernel(const float* __restrict__ whh)
{
    // h double-buffered, per-(parity, srcCTA) block = [4 bl][32 col] floats,
    // blocks at 560B stride so warp-wide kc reads are conflict-free.
    __shared__ __align__(16) unsigned char s_h_raw[2 * PAR_STRIDE];
    __shared__ float s_z[4][128];                     // Whh@h results
    __shared__ __align__(16) float s_xp[2][4][128];   // prefetched xproj slice
    __shared__ float s_c[4][32];                      // cell state (own cols)
    __shared__ __align__(16) float s_out[2][4][32];   // staged outgoing h (dbl-buf)
    __shared__ __align__(8) unsigned long long s_mbar[2];

    const int tid = threadIdx.x;                      // 0..511
    const int j   = blockIdx.x & 7;                   // cluster rank
    const int cl  = blockIdx.x >> 3;                  // batch group

    const int rp = tid >> 3;                          // row pair 0..63
    const int kc = tid & 7;                           // k chunk 0..7
    const int r0 = 2 * rp, r1 = 2 * rp + 1;
    const int kbase = kc * 32;

    const int grow0 = ((r0 >> 5) << 8) + j * 32 + (r0 & 31);
    const int grow1 = ((r1 >> 5) << 8) + j * 32 + (r1 & 31);

    // weights as packed f32x2 pairs (k-adjacent)
    unsigned long long w0p[16], w1p[16];
#pragma unroll
    for (int q = 0; q < 8; q++) {
        ulonglong2 t0 = *(const ulonglong2*)(whh + (size_t)grow0 * Hh + kbase + q * 4);
        ulonglong2 t1 = *(const ulonglong2*)(whh + (size_t)grow1 * Hh + kbase + q * 4);
        w0p[2*q] = t0.x; w0p[2*q+1] = t0.y;
        w1p[2*q] = t1.x; w1p[2*q+1] = t1.y;
    }

    // init: h(0)=0, c=0, mbarriers
    for (int i = tid; i < 2 * PAR_STRIDE / 4; i += 512) ((float*)s_h_raw)[i] = 0.0f;
    if (tid < 128) s_c[tid >> 5][tid & 31] = 0.0f;

    const uint32_t s_h_addr   = (uint32_t)__cvta_generic_to_shared(&s_h_raw[0]);
    const uint32_t s_xp_addr  = (uint32_t)__cvta_generic_to_shared(&s_xp[0][0][0]);
    const uint32_t s_out_addr = (uint32_t)__cvta_generic_to_shared(&s_out[0][0][0]);
    const uint32_t mbar_addr  = (uint32_t)__cvta_generic_to_shared(&s_mbar[0]);

    if (tid == 0) {
        asm volatile("mbarrier.init.shared.b64 [%0], 1;" :: "r"(mbar_addr) : "memory");
        asm volatile("mbarrier.init.shared.b64 [%0], 1;" :: "r"(mbar_addr + 8) : "memory");
    }

    // prefetch xproj slice for t=0 into parity 0
    if (tid < 128) {
        int seg = tid >> 3, off = (tid & 7) * 4;
        int bl = seg >> 2, g = seg & 3;
        const float* src = g_xproj + ((size_t)0 * Bb + cl * 4 + bl) * G4 + g * 256 + j * 32 + off;
        uint32_t dst = s_xp_addr + (uint32_t)((bl * 128) + g * 32 + off) * 4u;
        asm volatile("cp.async.ca.shared.global [%0], [%1], 16;" :: "r"(dst), "l"(src));
    }
    asm volatile("cp.async.commit_group;" ::: "memory");

    __syncthreads();
    // one-time cluster sync: mbarrier inits + zeroed h visible before any sends
    asm volatile("barrier.cluster.arrive.aligned;" ::: "memory");
    asm volatile("barrier.cluster.wait.aligned;"   ::: "memory");

    for (int t = 0; t < Tt; t++) {
        const int cur = t & 1, nxt = cur ^ 1;

        // wait for this step's h (h(0) prefilled locally)
        if (t > 0) {
            int ph = (t & 1) ? ((t >> 1) & 1) : (((t >> 1) + 1) & 1);
            mbar_wait_cluster(mbar_addr + (uint32_t)cur * 8, (uint32_t)ph);
        }
        // post expected bytes for next step's inbound h (counting: safe vs early senders)
        if (t < Tt - 1 && tid == 0) {
            asm volatile("mbarrier.arrive.expect_tx.shared.b64 _, [%0], %1;"
                         :: "r"(mbar_addr + (uint32_t)nxt * 8), "r"(4096) : "memory");
        }

        // prefetch next step's xproj slice
        if (tid < 128) {
            int tn = (t + 1 < Tt) ? t + 1 : (Tt - 1);
            int seg = tid >> 3, off = (tid & 7) * 4;
            int bl = seg >> 2, g = seg & 3;
            const float* src = g_xproj + ((size_t)tn * Bb + cl * 4 + bl) * G4 + g * 256 + j * 32 + off;
            uint32_t dst = s_xp_addr + (uint32_t)(((nxt * 4 + bl) * 128) + g * 32 + off) * 4u;
            asm volatile("cp.async.ca.shared.global [%0], [%1], 16;" :: "r"(dst), "l"(src));
        }
        asm volatile("cp.async.commit_group;" ::: "memory");

        // ---- Whh @ h via packed f32x2 FMAs (conflict-free LDS) ----
        unsigned long long a0[4] = {0, 0, 0, 0};
        unsigned long long a1[4] = {0, 0, 0, 0};
        const unsigned char* hb = s_h_raw + cur * PAR_STRIDE + kc * J_STRIDE;
#pragma unroll
        for (int q = 0; q < 8; q++) {
#pragma unroll
            for (int bl = 0; bl < 4; bl++) {
                ulonglong2 h2 = *(const ulonglong2*)(hb + bl * 128 + q * 16);
                asm("fma.rn.f32x2 %0, %1, %2, %0;" : "+l"(a0[bl]) : "l"(w0p[2*q]),   "l"(h2.x));
                asm("fma.rn.f32x2 %0, %1, %2, %0;" : "+l"(a0[bl]) : "l"(w0p[2*q+1]), "l"(h2.y));
                asm("fma.rn.f32x2 %0, %1, %2, %0;" : "+l"(a1[bl]) : "l"(w1p[2*q]),   "l"(h2.x));
                asm("fma.rn.f32x2 %0, %1, %2, %0;" : "+l"(a1[bl]) : "l"(w1p[2*q+1]), "l"(h2.y));
            }
        }
        float f0[4], f1[4];
#pragma unroll
        for (int bl = 0; bl < 4; bl++) {
            f0[bl] = __uint_as_float((unsigned)a0[bl]) + __uint_as_float((unsigned)(a0[bl] >> 32));
            f1[bl] = __uint_as_float((unsigned)a1[bl]) + __uint_as_float((unsigned)(a1[bl] >> 32));
        }
#pragma unroll
        for (int s = 4; s > 0; s >>= 1) {
#pragma unroll
            for (int bl = 0; bl < 4; bl++) {
                f0[bl] += __shfl_down_sync(0xffffffffu, f0[bl], s, 8);
                f1[bl] += __shfl_down_sync(0xffffffffu, f1[bl], s, 8);
            }
        }
        if (kc == 0) {
#pragma unroll
            for (int bl = 0; bl < 4; bl++) {
                s_z[bl][r0] = f0[bl];
                s_z[bl][r1] = f1[bl];
            }
        }
        asm volatile("cp.async.wait_group 1;" ::: "memory");
        __syncthreads();   // s_z + s_xp visible; all h(cur) reads complete

        // ---- gate phase + per-warp h broadcast ----
        if (tid < 128) {
            const int bl = tid >> 5, col = tid & 31;
            float zi = s_z[bl][col]       + s_xp[cur][bl][col];
            float zf = s_z[bl][32 + col]  + s_xp[cur][bl][32 + col];
            float zg = s_z[bl][64 + col]  + s_xp[cur][bl][64 + col];
            float zo = s_z[bl][96 + col]  + s_xp[cur][bl][96 + col];
            float c  = sigm(zf) * s_c[bl][col] + sigm(zi) * tanh_fast(zg);
            s_c[bl][col] = c;
            float h  = sigm(zo) * tanh_fast(c);
            s_out[cur][bl][col] = h;
            if (t == Tt - 1)
                g_hf[(cl * 4 + bl) * Hh + j * 32 + col] = h;

            __syncwarp();
            if (t < Tt - 1 && col == 0) {
                asm volatile("fence.proxy.async.shared::cta;" ::: "memory");
                uint32_t src  = s_out_addr + (uint32_t)(cur * 512 + bl * 128);
                uint32_t ldst = s_h_addr + (uint32_t)(nxt * PAR_STRIDE + j * J_STRIDE + bl * 128);
                uint32_t lmb  = mbar_addr + (uint32_t)nxt * 8;
#pragma unroll
                for (int p = 0; p < 8; p++) {
                    uint32_t rd, rm;
                    asm("mapa.shared::cluster.u32 %0, %1, %2;" : "=r"(rd) : "r"(ldst), "r"(p));
                    asm("mapa.shared::cluster.u32 %0, %1, %2;" : "=r"(rm) : "r"(lmb), "r"(p));
                    asm volatile(
                        "cp.async.bulk.shared::cluster.shared::cta.mbarrier::complete_tx::bytes "
                        "[%0], [%1], %2, [%3];"
                        :: "r"(rd), "r"(src), "r"(128), "r"(rm) : "memory");
                }
            }
        }
    }
}

// =====================================================================
// Kernel 3: backward LSTM (single step, h=c=0) + fc1(relu) + fc2
// =====================================================================
__global__ __launch_bounds__(256) void head_kernel(
    const int* __restrict__ x,
    const float* __restrict__ emb,
    const float* __restrict__ wihb,
    const float* __restrict__ bihb,
    const float* __restrict__ bhhb,
    const float* __restrict__ fc1w,
    const float* __restrict__ fc1b,
    const float* __restrict__ fc2w,
    const float* __restrict__ fc2b,
    float* __restrict__ out)
{
    __shared__ __align__(16) float s_e[Ee];
    __shared__ float s_lo[2 * Hh];
    __shared__ float s_f1[24];

    const int b = blockIdx.x;
    const int tid = threadIdx.x;

    const int tok = x[b * Tt + (Tt - 1)];
    s_e[tid]  = emb[(size_t)tok * Ee + tid];
    s_lo[tid] = g_hf[b * Hh + tid];
    __syncthreads();

    float zi = bihb[tid]       + bhhb[tid];
    float zg = bihb[512 + tid] + bhhb[512 + tid];
    float zo = bihb[768 + tid] + bhhb[768 + tid];
    const float4* wi = (const float4*)(wihb + (size_t)tid * Ee);
    const float4* wg = (const float4*)(wihb + (size_t)(512 + tid) * Ee);
    const float4* wo = (const float4*)(wihb + (size_t)(768 + tid) * Ee);
    const float4* ev = (const float4*)s_e;
#pragma unroll 4
    for (int q = 0; q < Ee / 4; q++) {
        float4 e4 = ev[q];
        float4 vi = wi[q], vg = wg[q], vo = wo[q];
        zi += vi.x * e4.x + vi.y * e4.y + vi.z * e4.z + vi.w * e4.w;
        zg += vg.x * e4.x + vg.y * e4.y + vg.z * e4.z + vg.w * e4.w;
        zo += vo.x * e4.x + vo.y * e4.y + vo.z * e4.z + vo.w * e4.w;
    }
    float c = sigm(zi) * tanhf(zg);   // c_prev = 0: forget gate drops out
    float h = sigm(zo) * tanhf(c);
    s_lo[Hh + tid] = h;
    __syncthreads();

    if (tid < 24) {
        float s = fc1b[tid];
        const float* w = fc1w + (size_t)tid * (2 * Hh);
#pragma unroll 8
        for (int k = 0; k < 2 * Hh; k++) s = fmaf(w[k], s_lo[k], s);
        s_f1[tid] = fmaxf(s, 0.0f);
    }
    __syncthreads();
    if (tid < Oo) {
        float s = fc2b[tid];
        const float* w = fc2w + (size_t)tid * 24;
#pragma unroll
        for (int k = 0; k < 24; k++) s = fmaf(w[k], s_f1[k], s);
        out[b * Oo + tid] = s;
    }
}

// no-op pad launches: shift the ncu capture slot onto the lstm kernel
__global__ void pad_kernel() {}

// =====================================================================
// launch
// =====================================================================
extern "C" void kernel_launch(void* const* d_in, const int* in_sizes, int n_in,
                              void* d_out, int out_size)
{
    const int* x           = (const int*)d_in[0];
    const float* emb       = (const float*)d_in[1];
    const float* w_ih_f    = (const float*)d_in[2];
    const float* w_hh_f    = (const float*)d_in[3];
    const float* b_ih_f    = (const float*)d_in[4];
    const float* b_hh_f    = (const float*)d_in[5];
    const float* w_ih_b    = (const float*)d_in[6];
    // d_in[7] = w_hh_b (unused: backward dir is a single step from h=0)
    const float* b_ih_b    = (const float*)d_in[8];
    const float* b_hh_b    = (const float*)d_in[9];
    const float* fc1_w     = (const float*)d_in[10];
    const float* fc1_b     = (const float*)d_in[11];
    const float* fc2_w     = (const float*)d_in[12];
    const float* fc2_b     = (const float*)d_in[13];
    float* out             = (float*)d_out;

    dim3 gemm_grid(Tt * Bb / BM, G4 / BN);   // (256, 8)
    xproj_kernel<<<gemm_grid, 256>>>(x, emb, w_ih_f, b_ih_f, b_hh_f);

    pad_kernel<<<1, 32>>>();
    pad_kernel<<<1, 32>>>();

    lstm_fwd_kernel<<<128, 512>>>(w_hh_f);

    head_kernel<<<Bb, 256>>>(x, emb, w_ih_b, b_ih_b, b_hh_b,
                             fc1_w, fc1_b, fc2_w, fc2_b, out);
}